// round 15
// baseline (speedup 1.0000x reference)
#include <cuda_runtime.h>
#include <cuda_bf16.h>
#include <cstdint>

#define T_STEPS 1024
#define B_SZ    32
#define I_SZ    512
#define H_SZ    512
#define G4      2048                 // 4*H
#define TBH     (T_STEPS * B_SZ * H_SZ)
#define BH      (B_SZ * H_SZ)
#define NG      4                    // independent batch groups (8 batches each)
#define NC      32                   // CTAs per group
#define NCH     16                   // CTAs per half-barrier
#define MROWS   (T_STEPS * B_SZ)     // 32768

typedef unsigned long long ull;

// ---------------- device scratch (no allocation allowed) ----------------
__device__ float g_gates[(size_t)T_STEPS * B_SZ * G4];   // [t][b][p], p = 4j+g
__device__ float g_wih_p[G4 * I_SZ];                     // packed W_ih (p = 4j+g)
__device__ float g_bias_p[G4];                           // b_ih + b_hh, packed
__device__ unsigned g_hpkHi[NG * 2 * 2048];              // [grp][ph][k2][b8] bf16x2 hi
__device__ unsigned g_hpkLo[NG * 2 * 2048];              // [grp][ph][k2][b8] bf16x2 lo
__device__ unsigned g_cnt[NG * 2 * 32];                  // per-(group,half) arrival counters
__device__ unsigned g_gen2[NG * 2 * 32];                 // per-(group,half) generation
// W_hh HMMA fragments (per CTA: 16384 u32; frag i=ka(0..15), warp=kh*4+ma)
__device__ unsigned g_wfragHi[NC * 16384];
__device__ unsigned g_wfragLo[NC * 16384];
// bf16x3 GEMM operands
__device__ __nv_bfloat16 g_Ahi[(size_t)MROWS * I_SZ];
__device__ __nv_bfloat16 g_Alo[(size_t)MROWS * I_SZ];
__device__ __nv_bfloat16 g_Whi[G4 * I_SZ];
__device__ __nv_bfloat16 g_Wlo[G4 * I_SZ];

// ---------------- helpers ----------------
__device__ __forceinline__ float2 unpack2(ull v) {
    float2 r; asm("mov.b64 {%0, %1}, %2;" : "=f"(r.x), "=f"(r.y) : "l"(v)); return r;
}
__device__ __forceinline__ ull packf2(float a, float b) {
    ull r; asm("mov.b64 %0, {%1, %2};" : "=l"(r) : "f"(a), "f"(b)); return r;
}
__device__ __forceinline__ unsigned ld_acq(const unsigned* p) {
    unsigned v; asm volatile("ld.acquire.gpu.global.u32 %0, [%1];" : "=r"(v) : "l"(p) : "memory");
    return v;
}
__device__ __forceinline__ void st_rel(unsigned* p, unsigned v) {
    asm volatile("st.release.gpu.global.u32 [%0], %1;" :: "l"(p), "r"(v) : "memory");
}
__device__ __forceinline__ unsigned atom_add_rel(unsigned* p, unsigned v) {
    unsigned old;
    asm volatile("atom.add.release.gpu.global.u32 %0, [%1], %2;"
                 : "=r"(old) : "l"(p), "r"(v) : "memory");
    return old;
}
__device__ __forceinline__ float sigf(float x) {
    return __fdividef(1.f, 1.f + __expf(-x));
}
__device__ __forceinline__ float tanh_fast(float x) {
    float ax = fabsf(x);
    float e  = __expf(-2.f * ax);
    float r  = __fdividef(1.f - e, 1.f + e);
    return copysignf(r, x);
}
__device__ __forceinline__ void mma16816(float* c, const unsigned* a, const unsigned* b) {
    asm volatile(
        "mma.sync.aligned.m16n8k16.row.col.f32.bf16.bf16.f32 "
        "{%0,%1,%2,%3}, {%4,%5,%6,%7}, {%8,%9}, {%0,%1,%2,%3};"
        : "+f"(c[0]), "+f"(c[1]), "+f"(c[2]), "+f"(c[3])
        : "r"(a[0]), "r"(a[1]), "r"(a[2]), "r"(a[3]), "r"(b[0]), "r"(b[1]));
}
// fp32 pair -> packed bf16 hi + residual lo (low 16 bits = first element)
#define CVT2(f0, f1, HI, LO) do {                                   \
    __nv_bfloat162 _h = __floats2bfloat162_rn((f0), (f1));          \
    float _r0 = (f0) - __low2float(_h);                             \
    float _r1 = (f1) - __high2float(_h);                            \
    __nv_bfloat162 _l = __floats2bfloat162_rn(_r0, _r1);            \
    (HI) = *(unsigned*)&_h; (LO) = *(unsigned*)&_l;                 \
} while (0)

// ---------------- prep: pack W_ih, W_hh fragments (NEW layout), packed h0, sync -------
__global__ void prep_kernel(const float* __restrict__ Wih, const float* __restrict__ Whh,
                            const float* __restrict__ bih, const float* __restrict__ bhh,
                            const float* __restrict__ h0) {
    int p = blockIdx.x;                     // packed row p = 4j + g
    int g = p & 3, j = p >> 2;
    int orig = g * H_SZ + j;

    const float* srcI = Wih + (size_t)orig * I_SZ;
    float* dI = g_wih_p + (size_t)p * I_SZ;
    for (int k = threadIdx.x; k < I_SZ; k += blockDim.x) dI[k] = srcI[k];

    // W_hh -> per-thread HMMA fragment order, warp = kh*4 + ma, frag index = ka (0..15).
    const float* srcH = Whh + (size_t)orig * H_SZ;
    int cc = p >> 6, r = p & 63;
    int ma = r >> 4, rr = r & 15;
    for (int k = threadIdx.x; k < H_SZ; k += blockDim.x) {
        float w = srcH[k];
        __nv_bfloat16 hb = __float2bfloat16(w);
        __nv_bfloat16 lb = __float2bfloat16(w - __bfloat162float(hb));
        int kh = k >> 8, kaL = (k >> 4) & 15, kin = k & 15;
        int wrp = kh * 4 + ma;
        int q = (rr >= 8 ? 1 : 0) + (kin >= 8 ? 2 : 0);
        int lane = (rr & 7) * 4 + ((kin & 7) >> 1);
        size_t u16idx = (((size_t)cc * 16384 + (kaL * 256 + wrp * 32 + lane) * 4 + q) << 1)
                        + (k & 1);
        ((unsigned short*)g_wfragHi)[u16idx] = __bfloat16_as_ushort(hb);
        ((unsigned short*)g_wfragLo)[u16idx] = __bfloat16_as_ushort(lb);
    }
    if (threadIdx.x == 0) g_bias_p[p] = bih[orig] + bhh[orig];

    // h0 -> packed bf16 hi/lo pairs, consumer layout [grp][0][k2][b8]
    if (p < H_SZ && !(p & 1)) {
        for (int b = threadIdx.x; b < B_SZ; b += blockDim.x) {
            unsigned hi, lo;
            CVT2(h0[(size_t)b * H_SZ + p], h0[(size_t)b * H_SZ + p + 1], hi, lo);
            int idx = (b >> 3) * 2 * 2048 + (p >> 1) * 8 + (b & 7);
            g_hpkHi[idx] = hi; g_hpkLo[idx] = lo;
        }
    }
    if (p < NG * 2 && threadIdx.x == 0) { g_cnt[p * 32] = 0; g_gen2[p * 32] = 0; }
}

// ---------------- convert: fp32 -> bf16 hi/lo for A (input) and packed W_ih ------------
__global__ __launch_bounds__(256) void convert_kernel(const float* __restrict__ input) {
    int bid = blockIdx.x;
    const float* src;
    __nv_bfloat16 *dhi, *dlo;
    size_t i;
    if (bid < 8192) {
        i = ((size_t)bid * 256 + threadIdx.x) * 8;
        src = input; dhi = g_Ahi; dlo = g_Alo;
    } else {
        i = ((size_t)(bid - 8192) * 256 + threadIdx.x) * 8;
        src = g_wih_p; dhi = g_Whi; dlo = g_Wlo;
    }
    float4 x0 = *(const float4*)(src + i);
    float4 x1 = *(const float4*)(src + i + 4);
    float v[8] = {x0.x, x0.y, x0.z, x0.w, x1.x, x1.y, x1.z, x1.w};
    unsigned hs[4], ls[4];
#pragma unroll
    for (int k = 0; k < 4; k++) CVT2(v[2 * k], v[2 * k + 1], hs[k], ls[k]);
    *(uint4*)(dhi + i) = make_uint4(hs[0], hs[1], hs[2], hs[3]);
    *(uint4*)(dlo + i) = make_uint4(ls[0], ls[1], ls[2], ls[3]);
}

// ---------------- phase 1: bf16x3 HMMA GEMM, register double-buffered (R14-exact) ------
#define GPITCH 40

__global__ __launch_bounds__(256) void gemm_tc_kernel() {
    __shared__ __nv_bfloat16 sAh[128][GPITCH];
    __shared__ __nv_bfloat16 sAl[128][GPITCH];
    __shared__ __nv_bfloat16 sBh[128][GPITCH];
    __shared__ __nv_bfloat16 sBl[128][GPITCH];

    int tid  = threadIdx.x;
    int lane = tid & 31, wid = tid >> 5;
    int wm = wid & 3, wn = wid >> 2;
    int mBase = blockIdx.y * 128;
    int nBase = blockIdx.x * 128;

    int lrow = tid >> 1, lhalf = tid & 1;

    float acc[2][8][4];
#pragma unroll
    for (int ma = 0; ma < 2; ma++)
#pragma unroll
        for (int na = 0; na < 8; na++)
#pragma unroll
            for (int q = 0; q < 4; q++) acc[ma][na][q] = 0.f;

    int fr = lane >> 2;
    int fc = (lane & 3) * 2;

    size_t gaRow = (size_t)(mBase + lrow) * I_SZ + lhalf * 16;
    size_t gbRow = (size_t)(nBase + lrow) * I_SZ + lhalf * 16;
    uint4 ra0 = __ldg((const uint4*)(g_Ahi + gaRow));
    uint4 ra1 = __ldg((const uint4*)(g_Ahi + gaRow) + 1);
    uint4 rl0 = __ldg((const uint4*)(g_Alo + gaRow));
    uint4 rl1 = __ldg((const uint4*)(g_Alo + gaRow) + 1);
    uint4 rb0 = __ldg((const uint4*)(g_Whi + gbRow));
    uint4 rb1 = __ldg((const uint4*)(g_Whi + gbRow) + 1);
    uint4 rq0 = __ldg((const uint4*)(g_Wlo + gbRow));
    uint4 rq1 = __ldg((const uint4*)(g_Wlo + gbRow) + 1);

    for (int ks = 0; ks < I_SZ / 32; ks++) {
        *(uint4*)&sAh[lrow][lhalf * 16]     = ra0;
        *(uint4*)&sAh[lrow][lhalf * 16 + 8] = ra1;
        *(uint4*)&sAl[lrow][lhalf * 16]     = rl0;
        *(uint4*)&sAl[lrow][lhalf * 16 + 8] = rl1;
        *(uint4*)&sBh[lrow][lhalf * 16]     = rb0;
        *(uint4*)&sBh[lrow][lhalf * 16 + 8] = rb1;
        *(uint4*)&sBl[lrow][lhalf * 16]     = rq0;
        *(uint4*)&sBl[lrow][lhalf * 16 + 8] = rq1;
        __syncthreads();

        if (ks + 1 < I_SZ / 32) {
            size_t ga = gaRow + (ks + 1) * 32;
            size_t gb = gbRow + (ks + 1) * 32;
            ra0 = __ldg((const uint4*)(g_Ahi + ga));
            ra1 = __ldg((const uint4*)(g_Ahi + ga) + 1);
            rl0 = __ldg((const uint4*)(g_Alo + ga));
            rl1 = __ldg((const uint4*)(g_Alo + ga) + 1);
            rb0 = __ldg((const uint4*)(g_Whi + gb));
            rb1 = __ldg((const uint4*)(g_Whi + gb) + 1);
            rq0 = __ldg((const uint4*)(g_Wlo + gb));
            rq1 = __ldg((const uint4*)(g_Wlo + gb) + 1);
        }

#pragma unroll
        for (int ka = 0; ka < 2; ka++) {
            int kc = ka * 16 + fc;
            unsigned aH[2][4], aL[2][4];
#pragma unroll
            for (int ma = 0; ma < 2; ma++) {
                int r0 = wm * 32 + ma * 16 + fr;
                aH[ma][0] = *(const unsigned*)&sAh[r0][kc];
                aH[ma][1] = *(const unsigned*)&sAh[r0 + 8][kc];
                aH[ma][2] = *(const unsigned*)&sAh[r0][kc + 8];
                aH[ma][3] = *(const unsigned*)&sAh[r0 + 8][kc + 8];
                aL[ma][0] = *(const unsigned*)&sAl[r0][kc];
                aL[ma][1] = *(const unsigned*)&sAl[r0 + 8][kc];
                aL[ma][2] = *(const unsigned*)&sAl[r0][kc + 8];
                aL[ma][3] = *(const unsigned*)&sAl[r0 + 8][kc + 8];
            }
            unsigned bH[8][2], bL[8][2];
#pragma unroll
            for (int na = 0; na < 8; na++) {
                int n0 = wn * 64 + na * 8 + fr;
                bH[na][0] = *(const unsigned*)&sBh[n0][kc];
                bH[na][1] = *(const unsigned*)&sBh[n0][kc + 8];
                bL[na][0] = *(const unsigned*)&sBl[n0][kc];
                bL[na][1] = *(const unsigned*)&sBl[n0][kc + 8];
            }
#pragma unroll
            for (int ma = 0; ma < 2; ma++)
#pragma unroll
                for (int na = 0; na < 8; na++) {
                    mma16816(acc[ma][na], aH[ma], bH[na]);
                    mma16816(acc[ma][na], aH[ma], bL[na]);
                    mma16816(acc[ma][na], aL[ma], bH[na]);
                }
        }
        __syncthreads();
    }

#pragma unroll
    for (int ma = 0; ma < 2; ma++)
#pragma unroll
        for (int na = 0; na < 8; na++) {
            int row = mBase + wm * 32 + ma * 16 + fr;
            int col = nBase + wn * 64 + na * 8 + fc;
            float b0 = __ldg(&g_bias_p[col]);
            float b1 = __ldg(&g_bias_p[col + 1]);
            float* d0 = g_gates + (size_t)row * G4 + col;
            d0[0] = acc[ma][na][0] + b0;
            d0[1] = acc[ma][na][1] + b1;
            float* d1 = d0 + (size_t)8 * G4;
            d1[0] = acc[ma][na][2] + b0;
            d1[1] = acc[ma][na][3] + b1;
        }
}

// ---------------- phase 2: persistent scan (2-way K-split, half-aligned) --------------
// Warp wid = kh*4 + ma: m-atom ma (rows 16ma..16ma+15), K-half kh. Warps 0-3 consume
// only lo-staged data, 4-7 only hi. Hi warps dump 2KB partials (parity ping-pong) at
// one __syncthreads; warps 0-3 do a depth-2 reduce + sh_gate + epilogue + publish +
// arrival under bar.sync 1,128 while hi warps run ahead into the next step.
__global__ __launch_bounds__(256) void scan_kernel(const float* __restrict__ c0,
                                                   float* __restrict__ out, int out_size) {
    extern __shared__ float smem[];
    unsigned* shHi  = (unsigned*)smem;             // 2048 u32: [k2][b8] bf16x2 hi
    unsigned* shLo  = (unsigned*)(smem + 2048);    // 2048 u32
    ull*      sh_part = (ull*)(smem + 4096);       // 2 x 256 ull (parity) = 4KB
    float*    sh_gate = smem + 4096 + 1024;        // 64 rows * 10 floats

    int tid = threadIdx.x;
    int grp = blockIdx.x >> 5;
    int c   = blockIdx.x & 31;
    int lane = tid & 31, wid = tid >> 5;
    int kh = wid >> 2, ma = wid & 3;

    // W_hh fragments -> registers (frag i = ka 0..15 for this warp's (kh, ma))
    uint4 wHi[16], wLo[16];
    {
        const uint4* fh = ((const uint4*)g_wfragHi) + c * 4096;
        const uint4* fl = ((const uint4*)g_wfragLo) + c * 4096;
#pragma unroll
        for (int i = 0; i < 16; i++) {
            wHi[i] = __ldg(fh + i * 256 + tid);
            wLo[i] = __ldg(fl + i * 256 + tid);
        }
    }

    int b8 = tid >> 4, jl = tid & 15;            // epilogue mapping (tid < 128)
    float c_val = 0.f;
    const float* gxp = g_gates;
    if (tid < 128) {
        c_val = c0[(size_t)(grp * 8 + b8) * H_SZ + c * 16 + jl];
        gxp   = g_gates + (size_t)(grp * 8 + b8) * G4 + c * 64 + jl * 4;
    }
    int myhalf = c >> 4;
    unsigned* cntA   = &g_cnt [(grp * 2 + myhalf) * 32];
    unsigned* genOwn = &g_gen2[(grp * 2 + myhalf) * 32];
    unsigned* genLo  = &g_gen2[(grp * 2 + 0) * 32];
    unsigned* genHi  = &g_gen2[(grp * 2 + 1) * 32];
    unsigned* gHi = g_hpkHi + grp * 2 * 2048;
    unsigned* gLo = g_hpkLo + grp * 2 * 2048;

    int fr = lane >> 2, bcol = (lane & 3) * 2;

    for (int t = 0; t < T_STEPS; t++) {
        float4 gxv = make_float4(0.f, 0.f, 0.f, 0.f);
        if (tid < 128) gxv = __ldg((const float4*)(gxp + (size_t)t * B_SZ * G4));

        // ---- per-half wait + stage packed hi/lo ----
        const uint4* hHi4 = (const uint4*)(gHi + (t & 1) * 2048);
        const uint4* hLo4 = (const uint4*)(gLo + (t & 1) * 2048);
        if (tid < 128) {
            if (tid == 0) { while (ld_acq(genLo) < (unsigned)t) {} }
            asm volatile("bar.sync 1, 128;" ::: "memory");
            ((uint4*)shHi)[tid]       = __ldcg(hHi4 + tid);
            ((uint4*)shHi)[tid + 128] = __ldcg(hHi4 + tid + 128);
            ((uint4*)shLo)[tid]       = __ldcg(hLo4 + tid);
            ((uint4*)shLo)[tid + 128] = __ldcg(hLo4 + tid + 128);
            asm volatile("bar.sync 1, 128;" ::: "memory");
        } else {
            int tl = tid - 128;
            if (tl == 0) { while (ld_acq(genHi) < (unsigned)t) {} }
            asm volatile("bar.sync 2, 128;" ::: "memory");
            ((uint4*)shHi)[256 + tl] = __ldcg(hHi4 + 256 + tl);
            ((uint4*)shHi)[384 + tl] = __ldcg(hHi4 + 384 + tl);
            ((uint4*)shLo)[256 + tl] = __ldcg(hLo4 + 256 + tl);
            ((uint4*)shLo)[384 + tl] = __ldcg(hLo4 + 384 + tl);
            asm volatile("bar.sync 2, 128;" ::: "memory");
        }

        // ---- HMMA: 1 m-atom x 16 k-atoms x 3 passes, 3 independent chains ----
        float ahh[4] = {0.f, 0.f, 0.f, 0.f};
        float ahl[4] = {0.f, 0.f, 0.f, 0.f};
        float alh[4] = {0.f, 0.f, 0.f, 0.f};
        int n = lane >> 2;
#pragma unroll
        for (int ka = 0; ka < 16; ka++) {
            int k2b = kh * 128 + ka * 8 + (lane & 3);
            unsigned bh[2] = { shHi[k2b * 8 + n], shHi[(k2b + 4) * 8 + n] };
            unsigned bl[2] = { shLo[k2b * 8 + n], shLo[(k2b + 4) * 8 + n] };
            const unsigned* aH = (const unsigned*)&wHi[ka];
            const unsigned* aL = (const unsigned*)&wLo[ka];
            mma16816(ahh, aH, bh);
            mma16816(ahl, aH, bl);
            mma16816(alh, aL, bh);
        }
        float s0 = ahh[0] + ahl[0] + alh[0];
        float s1 = ahh[1] + ahl[1] + alh[1];
        float s2 = ahh[2] + ahl[2] + alh[2];
        float s3 = ahh[3] + ahl[3] + alh[3];

        // ---- hi warps dump partials (parity buffer), everyone syncs once ----
        ull* pb = sh_part + (t & 1) * 256;
        if (kh == 1) {
            pb[(ma * 32 + lane) * 2]     = packf2(s0, s1);
            pb[(ma * 32 + lane) * 2 + 1] = packf2(s2, s3);
        }
        __syncthreads();

        if (tid < 128) {
            // ---- depth-2 reduce + sh_gate write ----
            float2 f0 = unpack2(pb[(ma * 32 + lane) * 2]);
            float2 f1 = unpack2(pb[(ma * 32 + lane) * 2 + 1]);
            s0 += f0.x; s1 += f0.y; s2 += f1.x; s3 += f1.y;
            *(ull*)&sh_gate[(ma * 16 + fr) * 10 + bcol]     = packf2(s0, s1);
            *(ull*)&sh_gate[(ma * 16 + fr + 8) * 10 + bcol] = packf2(s2, s3);
            asm volatile("bar.sync 1, 128;" ::: "memory");

            // ---- epilogue + producer-side bf16 packing ----
            const float* gr = sh_gate + (4 * jl) * 10 + b8;
            float pi = gr[0]  + gxv.x;
            float pf = gr[10] + gxv.y;
            float pg = gr[20] + gxv.z;
            float po = gr[30] + gxv.w;
            float ig = sigf(pi), fg = sigf(pf), og = sigf(po);
            float gg = tanh_fast(pg);
            c_val = fg * c_val + ig * gg;
            float h_new = og * tanh_fast(c_val);
            float hp = __shfl_xor_sync(0xffffffffu, h_new, 1);
            if (!(jl & 1)) {
                unsigned hi, lo;
                CVT2(h_new, hp, hi, lo);
                int idx = ((t + 1) & 1) * 2048 + (c * 8 + (jl >> 1)) * 8 + b8;
                gHi[idx] = hi; gLo[idx] = lo;
            }
            asm volatile("bar.sync 1, 128;" ::: "memory");   // publishes done (lo threads)

            if (tid == 0) {
                unsigned arrived = atom_add_rel(cntA, 1u) + 1u;
                if (arrived == (unsigned)(t + 1) * (unsigned)NCH)
                    st_rel(genOwn, (unsigned)(t + 1));
            }
            out[(size_t)t * BH + (size_t)(grp * 8 + b8) * H_SZ + c * 16 + jl] = h_new;
            if (t == T_STEPS - 1 && out_size >= TBH + 2 * BH) {
                out[TBH + (grp * 8 + b8) * H_SZ + c * 16 + jl]      = h_new;  // h_f
                out[TBH + BH + (grp * 8 + b8) * H_SZ + c * 16 + jl] = c_val;  // c_f
            }
        }
        // hi warps run ahead to t+1 (gated by genHi; sh_part parity avoids the race)
    }
}

// ---------------- launch ----------------
extern "C" void kernel_launch(void* const* d_in, const int* in_sizes, int n_in,
                              void* d_out, int out_size) {
    const float* input = (const float*)d_in[0];
    const float* h0    = (const float*)d_in[1];
    const float* c0    = (const float*)d_in[2];
    const float* Wih   = (const float*)d_in[3];
    const float* Whh   = (const float*)d_in[4];
    const float* bih   = (const float*)d_in[5];
    const float* bhh   = (const float*)d_in[6];
    float* out = (float*)d_out;

    prep_kernel<<<G4, 128>>>(Wih, Whh, bih, bhh, h0);
    convert_kernel<<<8192 + 512, 256>>>(input);

    dim3 gridG(G4 / 128, MROWS / 128);
    gemm_tc_kernel<<<gridG, 256>>>();

    const int scan_smem = (4096 + 1024 + 640) * (int)sizeof(float);  // 23040 B
    cudaFuncSetAttribute(scan_kernel, cudaFuncAttributeMaxDynamicSharedMemorySize, scan_smem);
    scan_kernel<<<NG * NC, 256, scan_smem>>>(c0, out, out_size);
}

// round 16
// speedup vs baseline: 1.2535x; 1.2535x over previous
#include <cuda_runtime.h>
#include <cuda_bf16.h>
#include <cstdint>

#define T_STEPS 1024
#define B_SZ    32
#define I_SZ    512
#define H_SZ    512
#define G4      2048                 // 4*H
#define TBH     (T_STEPS * B_SZ * H_SZ)
#define BH      (B_SZ * H_SZ)
#define NG      4                    // independent batch groups (8 batches each)
#define NC      32                   // CTAs per group
#define NCH     16                   // CTAs per half-barrier
#define MROWS   (T_STEPS * B_SZ)     // 32768

typedef unsigned long long ull;

// ---------------- device scratch (no allocation allowed) ----------------
__device__ float g_gates[(size_t)T_STEPS * B_SZ * G4];   // [t][b][p], p = 4j+g
__device__ float g_wih_p[G4 * I_SZ];                     // packed W_ih (p = 4j+g)
__device__ float g_bias_p[G4];                           // b_ih + b_hh, packed
__device__ unsigned g_hpkHi[NG * 2 * 2048];              // [grp][ph][k2][b8] bf16x2 hi
__device__ unsigned g_hpkLo[NG * 2 * 2048];              // [grp][ph][k2][b8] bf16x2 lo
__device__ unsigned g_cnt[NG * 2 * 32];                  // per-(group,half) arrival counters
// W_hh HMMA fragments (per CTA: 16384 u32, uint4-ordered per thread) — R13/R14 layout
__device__ unsigned g_wfragHi[NC * 16384];
__device__ unsigned g_wfragLo[NC * 16384];
// bf16x3 GEMM operands
__device__ __nv_bfloat16 g_Ahi[(size_t)MROWS * I_SZ];
__device__ __nv_bfloat16 g_Alo[(size_t)MROWS * I_SZ];
__device__ __nv_bfloat16 g_Whi[G4 * I_SZ];
__device__ __nv_bfloat16 g_Wlo[G4 * I_SZ];

// ---------------- helpers ----------------
__device__ __forceinline__ void fadd2(ull &d, ull a) {
    asm("add.rn.f32x2 %0, %1, %2;" : "=l"(d) : "l"(d), "l"(a));
}
__device__ __forceinline__ float2 unpack2(ull v) {
    float2 r; asm("mov.b64 {%0, %1}, %2;" : "=f"(r.x), "=f"(r.y) : "l"(v)); return r;
}
__device__ __forceinline__ ull packf2(float a, float b) {
    ull r; asm("mov.b64 %0, {%1, %2};" : "=l"(r) : "f"(a), "f"(b)); return r;
}
__device__ __forceinline__ unsigned ld_acq(const unsigned* p) {
    unsigned v; asm volatile("ld.acquire.gpu.global.u32 %0, [%1];" : "=r"(v) : "l"(p) : "memory");
    return v;
}
__device__ __forceinline__ unsigned atom_add_rel(unsigned* p, unsigned v) {
    unsigned old;
    asm volatile("atom.add.release.gpu.global.u32 %0, [%1], %2;"
                 : "=r"(old) : "l"(p), "r"(v) : "memory");
    return old;
}
__device__ __forceinline__ float sigf(float x) {
    return __fdividef(1.f, 1.f + __expf(-x));
}
__device__ __forceinline__ float tanh_fast(float x) {
    float ax = fabsf(x);
    float e  = __expf(-2.f * ax);
    float r  = __fdividef(1.f - e, 1.f + e);
    return copysignf(r, x);
}
__device__ __forceinline__ void mma16816(float* c, const unsigned* a, const unsigned* b) {
    asm volatile(
        "mma.sync.aligned.m16n8k16.row.col.f32.bf16.bf16.f32 "
        "{%0,%1,%2,%3}, {%4,%5,%6,%7}, {%8,%9}, {%0,%1,%2,%3};"
        : "+f"(c[0]), "+f"(c[1]), "+f"(c[2]), "+f"(c[3])
        : "r"(a[0]), "r"(a[1]), "r"(a[2]), "r"(a[3]), "r"(b[0]), "r"(b[1]));
}
// fp32 pair -> packed bf16 hi + residual lo (low 16 bits = first element)
#define CVT2(f0, f1, HI, LO) do {                                   \
    __nv_bfloat162 _h = __floats2bfloat162_rn((f0), (f1));          \
    float _r0 = (f0) - __low2float(_h);                             \
    float _r1 = (f1) - __high2float(_h);                            \
    __nv_bfloat162 _l = __floats2bfloat162_rn(_r0, _r1);            \
    (HI) = *(unsigned*)&_h; (LO) = *(unsigned*)&_l;                 \
} while (0)

// ---------------- prep: pack W_ih, W_hh fragments (R13/R14 layout), packed h0, sync ----
__global__ void prep_kernel(const float* __restrict__ Wih, const float* __restrict__ Whh,
                            const float* __restrict__ bih, const float* __restrict__ bhh,
                            const float* __restrict__ h0) {
    int p = blockIdx.x;                     // packed row p = 4j + g
    int g = p & 3, j = p >> 2;
    int orig = g * H_SZ + j;

    const float* srcI = Wih + (size_t)orig * I_SZ;
    float* dI = g_wih_p + (size_t)p * I_SZ;
    for (int k = threadIdx.x; k < I_SZ; k += blockDim.x) dI[k] = srcI[k];

    // W_hh -> per-thread HMMA fragment order (bf16 hi/lo), R13/R14 layout
    const float* srcH = Whh + (size_t)orig * H_SZ;
    int cc = p >> 6, r = p & 63;
    int ma = r >> 4, rr = r & 15;
    for (int k = threadIdx.x; k < H_SZ; k += blockDim.x) {
        float w = srcH[k];
        __nv_bfloat16 hb = __float2bfloat16(w);
        __nv_bfloat16 lb = __float2bfloat16(w - __bfloat162float(hb));
        int kq = k >> 6, ka = (k >> 4) & 3, kin = k & 15;
        int q = (rr >= 8 ? 1 : 0) + (kin >= 8 ? 2 : 0);
        int lane = (rr & 7) * 4 + ((kin & 7) >> 1);
        size_t u16idx = (((size_t)cc * 16384 + ((ma * 4 + ka) * 256 + kq * 32 + lane) * 4 + q) << 1)
                        + (k & 1);
        ((unsigned short*)g_wfragHi)[u16idx] = __bfloat16_as_ushort(hb);
        ((unsigned short*)g_wfragLo)[u16idx] = __bfloat16_as_ushort(lb);
    }
    if (threadIdx.x == 0) g_bias_p[p] = bih[orig] + bhh[orig];

    // h0 -> packed bf16 hi/lo pairs, consumer layout [grp][0][k2][b8]
    if (p < H_SZ && !(p & 1)) {
        for (int b = threadIdx.x; b < B_SZ; b += blockDim.x) {
            unsigned hi, lo;
            CVT2(h0[(size_t)b * H_SZ + p], h0[(size_t)b * H_SZ + p + 1], hi, lo);
            int idx = (b >> 3) * 2 * 2048 + (p >> 1) * 8 + (b & 7);
            g_hpkHi[idx] = hi; g_hpkLo[idx] = lo;
        }
    }
    if (p < NG * 2 && threadIdx.x == 0) g_cnt[p * 32] = 0;
}

// ---------------- convert: fp32 -> bf16 hi/lo for A (input) and packed W_ih ------------
__global__ __launch_bounds__(256) void convert_kernel(const float* __restrict__ input) {
    int bid = blockIdx.x;
    const float* src;
    __nv_bfloat16 *dhi, *dlo;
    size_t i;
    if (bid < 8192) {
        i = ((size_t)bid * 256 + threadIdx.x) * 8;
        src = input; dhi = g_Ahi; dlo = g_Alo;
    } else {
        i = ((size_t)(bid - 8192) * 256 + threadIdx.x) * 8;
        src = g_wih_p; dhi = g_Whi; dlo = g_Wlo;
    }
    float4 x0 = *(const float4*)(src + i);
    float4 x1 = *(const float4*)(src + i + 4);
    float v[8] = {x0.x, x0.y, x0.z, x0.w, x1.x, x1.y, x1.z, x1.w};
    unsigned hs[4], ls[4];
#pragma unroll
    for (int k = 0; k < 4; k++) CVT2(v[2 * k], v[2 * k + 1], hs[k], ls[k]);
    *(uint4*)(dhi + i) = make_uint4(hs[0], hs[1], hs[2], hs[3]);
    *(uint4*)(dlo + i) = make_uint4(ls[0], ls[1], ls[2], ls[3]);
}

// ---------------- phase 1: bf16x3 HMMA GEMM, register double-buffered (R14-exact) ------
#define GPITCH 40

__global__ __launch_bounds__(256) void gemm_tc_kernel() {
    __shared__ __nv_bfloat16 sAh[128][GPITCH];
    __shared__ __nv_bfloat16 sAl[128][GPITCH];
    __shared__ __nv_bfloat16 sBh[128][GPITCH];
    __shared__ __nv_bfloat16 sBl[128][GPITCH];

    int tid  = threadIdx.x;
    int lane = tid & 31, wid = tid >> 5;
    int wm = wid & 3, wn = wid >> 2;
    int mBase = blockIdx.y * 128;
    int nBase = blockIdx.x * 128;

    int lrow = tid >> 1, lhalf = tid & 1;

    float acc[2][8][4];
#pragma unroll
    for (int ma = 0; ma < 2; ma++)
#pragma unroll
        for (int na = 0; na < 8; na++)
#pragma unroll
            for (int q = 0; q < 4; q++) acc[ma][na][q] = 0.f;

    int fr = lane >> 2;
    int fc = (lane & 3) * 2;

    size_t gaRow = (size_t)(mBase + lrow) * I_SZ + lhalf * 16;
    size_t gbRow = (size_t)(nBase + lrow) * I_SZ + lhalf * 16;
    uint4 ra0 = __ldg((const uint4*)(g_Ahi + gaRow));
    uint4 ra1 = __ldg((const uint4*)(g_Ahi + gaRow) + 1);
    uint4 rl0 = __ldg((const uint4*)(g_Alo + gaRow));
    uint4 rl1 = __ldg((const uint4*)(g_Alo + gaRow) + 1);
    uint4 rb0 = __ldg((const uint4*)(g_Whi + gbRow));
    uint4 rb1 = __ldg((const uint4*)(g_Whi + gbRow) + 1);
    uint4 rq0 = __ldg((const uint4*)(g_Wlo + gbRow));
    uint4 rq1 = __ldg((const uint4*)(g_Wlo + gbRow) + 1);

    for (int ks = 0; ks < I_SZ / 32; ks++) {
        *(uint4*)&sAh[lrow][lhalf * 16]     = ra0;
        *(uint4*)&sAh[lrow][lhalf * 16 + 8] = ra1;
        *(uint4*)&sAl[lrow][lhalf * 16]     = rl0;
        *(uint4*)&sAl[lrow][lhalf * 16 + 8] = rl1;
        *(uint4*)&sBh[lrow][lhalf * 16]     = rb0;
        *(uint4*)&sBh[lrow][lhalf * 16 + 8] = rb1;
        *(uint4*)&sBl[lrow][lhalf * 16]     = rq0;
        *(uint4*)&sBl[lrow][lhalf * 16 + 8] = rq1;
        __syncthreads();

        if (ks + 1 < I_SZ / 32) {
            size_t ga = gaRow + (ks + 1) * 32;
            size_t gb = gbRow + (ks + 1) * 32;
            ra0 = __ldg((const uint4*)(g_Ahi + ga));
            ra1 = __ldg((const uint4*)(g_Ahi + ga) + 1);
            rl0 = __ldg((const uint4*)(g_Alo + ga));
            rl1 = __ldg((const uint4*)(g_Alo + ga) + 1);
            rb0 = __ldg((const uint4*)(g_Whi + gb));
            rb1 = __ldg((const uint4*)(g_Whi + gb) + 1);
            rq0 = __ldg((const uint4*)(g_Wlo + gb));
            rq1 = __ldg((const uint4*)(g_Wlo + gb) + 1);
        }

#pragma unroll
        for (int ka = 0; ka < 2; ka++) {
            int kc = ka * 16 + fc;
            unsigned aH[2][4], aL[2][4];
#pragma unroll
            for (int ma = 0; ma < 2; ma++) {
                int r0 = wm * 32 + ma * 16 + fr;
                aH[ma][0] = *(const unsigned*)&sAh[r0][kc];
                aH[ma][1] = *(const unsigned*)&sAh[r0 + 8][kc];
                aH[ma][2] = *(const unsigned*)&sAh[r0][kc + 8];
                aH[ma][3] = *(const unsigned*)&sAh[r0 + 8][kc + 8];
                aL[ma][0] = *(const unsigned*)&sAl[r0][kc];
                aL[ma][1] = *(const unsigned*)&sAl[r0 + 8][kc];
                aL[ma][2] = *(const unsigned*)&sAl[r0][kc + 8];
                aL[ma][3] = *(const unsigned*)&sAl[r0 + 8][kc + 8];
            }
            unsigned bH[8][2], bL[8][2];
#pragma unroll
            for (int na = 0; na < 8; na++) {
                int n0 = wn * 64 + na * 8 + fr;
                bH[na][0] = *(const unsigned*)&sBh[n0][kc];
                bH[na][1] = *(const unsigned*)&sBh[n0][kc + 8];
                bL[na][0] = *(const unsigned*)&sBl[n0][kc];
                bL[na][1] = *(const unsigned*)&sBl[n0][kc + 8];
            }
#pragma unroll
            for (int ma = 0; ma < 2; ma++)
#pragma unroll
                for (int na = 0; na < 8; na++) {
                    mma16816(acc[ma][na], aH[ma], bH[na]);
                    mma16816(acc[ma][na], aH[ma], bL[na]);
                    mma16816(acc[ma][na], aL[ma], bH[na]);
                }
        }
        __syncthreads();
    }

#pragma unroll
    for (int ma = 0; ma < 2; ma++)
#pragma unroll
        for (int na = 0; na < 8; na++) {
            int row = mBase + wm * 32 + ma * 16 + fr;
            int col = nBase + wn * 64 + na * 8 + fc;
            float b0 = __ldg(&g_bias_p[col]);
            float b1 = __ldg(&g_bias_p[col + 1]);
            float* d0 = g_gates + (size_t)row * G4 + col;
            d0[0] = acc[ma][na][0] + b0;
            d0[1] = acc[ma][na][1] + b1;
            float* d1 = d0 + (size_t)8 * G4;
            d1[0] = acc[ma][na][2] + b0;
            d1[1] = acc[ma][na][3] + b1;
        }
}

// ---------------- phase 2: persistent scan (R14-exact + counter-direct 4-lane poll) ----
// Identical to the 3867us R14 scan except: the generation word is gone — consumers
// poll the arrival counter itself (cnt >= t*NCH, release-atomic / acquire-load pair
// gives ordering), and 4 lanes poll concurrently with __any_sync to cut the detect
// quantization from ~RTT to ~RTT/4.
__global__ __launch_bounds__(256) void scan_kernel(const float* __restrict__ c0,
                                                   float* __restrict__ out, int out_size) {
    extern __shared__ float smem[];
    unsigned* shHi  = (unsigned*)smem;             // 2048 u32: [k2][b8] bf16x2 hi
    unsigned* shLo  = (unsigned*)(smem + 2048);    // 2048 u32
    ull*      sh_part = (ull*)(smem + 4096);       // 256*9 ull (18 KB)
    float*    sh_gate = smem + 4096 + 4608;        // 64 rows * 10 floats

    int tid = threadIdx.x;
    int grp = blockIdx.x >> 5;
    int c   = blockIdx.x & 31;
    int lane = tid & 31, kq = tid >> 5;

    // W_hh fragments -> registers (constant for all 1024 steps)
    uint4 wHi[16], wLo[16];
    {
        const uint4* fh = ((const uint4*)g_wfragHi) + c * 4096;
        const uint4* fl = ((const uint4*)g_wfragLo) + c * 4096;
#pragma unroll
        for (int i = 0; i < 16; i++) {
            wHi[i] = __ldg(fh + i * 256 + tid);
            wLo[i] = __ldg(fl + i * 256 + tid);
        }
    }

    int b8 = tid >> 4, jl = tid & 15;            // epilogue mapping (tid < 128)
    float c_val = 0.f;
    const float* gxp = g_gates;
    if (tid < 128) {
        c_val = c0[(size_t)(grp * 8 + b8) * H_SZ + c * 16 + jl];
        gxp   = g_gates + (size_t)(grp * 8 + b8) * G4 + c * 64 + jl * 4;
    }
    int myhalf = c >> 4;
    unsigned* cntA  = &g_cnt[(grp * 2 + myhalf) * 32];
    unsigned* cntLo = &g_cnt[(grp * 2 + 0) * 32];
    unsigned* cntHi = &g_cnt[(grp * 2 + 1) * 32];
    unsigned* gHi = g_hpkHi + grp * 2 * 2048;
    unsigned* gLo = g_hpkLo + grp * 2 * 2048;

    for (int t = 0; t < T_STEPS; t++) {
        float4 gxv = make_float4(0.f, 0.f, 0.f, 0.f);
        if (tid < 128) gxv = __ldg((const float4*)(gxp + (size_t)t * B_SZ * G4));

        // ---- per-half wait (counter-direct, 4-lane poll) + stage packed hi/lo ----
        const uint4* hHi4 = (const uint4*)(gHi + (t & 1) * 2048);
        const uint4* hLo4 = (const uint4*)(gLo + (t & 1) * 2048);
        unsigned tgt = (unsigned)t * (unsigned)NCH;
        if (tid < 128) {
            if (tid < 4) {
                for (;;) { unsigned v = ld_acq(cntLo); if (__any_sync(0xFu, v >= tgt)) break; }
            }
            asm volatile("bar.sync 1, 128;" ::: "memory");
            ((uint4*)shHi)[tid]       = __ldcg(hHi4 + tid);
            ((uint4*)shHi)[tid + 128] = __ldcg(hHi4 + tid + 128);
            ((uint4*)shLo)[tid]       = __ldcg(hLo4 + tid);
            ((uint4*)shLo)[tid + 128] = __ldcg(hLo4 + tid + 128);
            asm volatile("bar.sync 1, 128;" ::: "memory");
        } else {
            int tl = tid - 128;
            if (tl < 4) {
                for (;;) { unsigned v = ld_acq(cntHi); if (__any_sync(0xFu, v >= tgt)) break; }
            }
            asm volatile("bar.sync 2, 128;" ::: "memory");
            ((uint4*)shHi)[256 + tl] = __ldcg(hHi4 + 256 + tl);
            ((uint4*)shHi)[384 + tl] = __ldcg(hHi4 + 384 + tl);
            ((uint4*)shLo)[256 + tl] = __ldcg(hLo4 + 256 + tl);
            ((uint4*)shLo)[384 + tl] = __ldcg(hLo4 + 384 + tl);
            asm volatile("bar.sync 2, 128;" ::: "memory");
        }

        // ---- HMMA bf16x3: 4 m-atoms x 4 k-atoms x 3 passes (R14-exact) ----
        float acc[4][4];
#pragma unroll
        for (int ma = 0; ma < 4; ma++)
#pragma unroll
            for (int q = 0; q < 4; q++) acc[ma][q] = 0.f;

        int n = lane >> 2;
#pragma unroll
        for (int ka = 0; ka < 4; ka++) {
            int k2b = kq * 32 + ka * 8 + (lane & 3);
            unsigned bh[2] = { shHi[k2b * 8 + n], shHi[(k2b + 4) * 8 + n] };
            unsigned bl[2] = { shLo[k2b * 8 + n], shLo[(k2b + 4) * 8 + n] };
#pragma unroll
            for (int ma = 0; ma < 4; ma++) {
                const unsigned* aH = (const unsigned*)&wHi[ma * 4 + ka];
                const unsigned* aL = (const unsigned*)&wLo[ma * 4 + ka];
                mma16816(acc[ma], aH, bh);
                mma16816(acc[ma], aH, bl);
                mma16816(acc[ma], aL, bh);
            }
        }

        // ---- dump partials, parallel cross-kq reduce (R14-exact) ----
        {
            ull* pp = sh_part + tid * 9;
#pragma unroll
            for (int ma = 0; ma < 4; ma++) {
                pp[ma * 2]     = packf2(acc[ma][0], acc[ma][1]);
                pp[ma * 2 + 1] = packf2(acc[ma][2], acc[ma][3]);
            }
        }
        __syncthreads();
        {
            int l = tid & 31, s = tid >> 5;
            ull v = sh_part[l * 9 + s];
#pragma unroll
            for (int k2 = 1; k2 < 8; k2++) fadd2(v, sh_part[((k2 << 5) + l) * 9 + s]);
            float2 vf = unpack2(v);
            int ma = s >> 1, half = s & 1;
            int row  = ma * 16 + (l >> 2) + 8 * half;
            int bcol = (l & 3) * 2;
            sh_gate[row * 10 + bcol]     = vf.x;
            sh_gate[row * 10 + bcol + 1] = vf.y;
        }
        __syncthreads();

        // ---- epilogue + producer-side bf16 packing (R14-exact) ----
        float h_new = 0.f;
        if (tid < 128) {
            const float* gr = sh_gate + (4 * jl) * 10 + b8;
            float pi = gr[0]  + gxv.x;
            float pf = gr[10] + gxv.y;
            float pg = gr[20] + gxv.z;
            float po = gr[30] + gxv.w;
            float ig = sigf(pi), fg = sigf(pf), og = sigf(po);
            float gg = tanh_fast(pg);
            c_val = fg * c_val + ig * gg;
            h_new = og * tanh_fast(c_val);
            float hp = __shfl_xor_sync(0xffffffffu, h_new, 1);
            if (!(jl & 1)) {                     // even jl packs (h_j, h_j+1)
                unsigned hi, lo;
                CVT2(h_new, hp, hi, lo);
                int idx = ((t + 1) & 1) * 2048 + (c * 8 + (jl >> 1)) * 8 + b8;
                gHi[idx] = hi; gLo[idx] = lo;
            }
        }

        // ---- arrival (release atomic IS the signal), then deferred out[] stores ----
        __syncthreads();                      // publish visible CTA-wide
        if (tid == 0) atom_add_rel(cntA, 1u);
        if (tid < 128) {
            out[(size_t)t * BH + (size_t)(grp * 8 + b8) * H_SZ + c * 16 + jl] = h_new;
            if (t == T_STEPS - 1 && out_size >= TBH + 2 * BH) {
                out[TBH + (grp * 8 + b8) * H_SZ + c * 16 + jl]      = h_new;  // h_f
                out[TBH + BH + (grp * 8 + b8) * H_SZ + c * 16 + jl] = c_val;  // c_f
            }
        }
        // no trailing __syncthreads (R14-exact)
    }
}

// ---------------- launch ----------------
extern "C" void kernel_launch(void* const* d_in, const int* in_sizes, int n_in,
                              void* d_out, int out_size) {
    const float* input = (const float*)d_in[0];
    const float* h0    = (const float*)d_in[1];
    const float* c0    = (const float*)d_in[2];
    const float* Wih   = (const float*)d_in[3];
    const float* Whh   = (const float*)d_in[4];
    const float* bih   = (const float*)d_in[5];
    const float* bhh   = (const float*)d_in[6];
    float* out = (float*)d_out;

    prep_kernel<<<G4, 128>>>(Wih, Whh, bih, bhh, h0);
    convert_kernel<<<8192 + 512, 256>>>(input);

    dim3 gridG(G4 / 128, MROWS / 128);
    gemm_tc_kernel<<<gridG, 256>>>();

    const int scan_smem = (4096 + 4608 + 640) * (int)sizeof(float);  // 37376 B
    cudaFuncSetAttribute(scan_kernel, cudaFuncAttributeMaxDynamicSharedMemorySize, scan_smem);
    scan_kernel<<<NG * NC, 256, scan_smem>>>(c0, out, out_size);
}

// round 17
// speedup vs baseline: 1.3607x; 1.0855x over previous
#include <cuda_runtime.h>
#include <cuda_bf16.h>
#include <cstdint>

#define T_STEPS 1024
#define B_SZ    32
#define I_SZ    512
#define H_SZ    512
#define G4      2048                 // 4*H
#define TBH     (T_STEPS * B_SZ * H_SZ)
#define BH      (B_SZ * H_SZ)
#define NG      4                    // independent batch groups (8 batches each)
#define NC      32                   // CTAs per group
#define NCQ     4                    // CTAs per quarter-barrier
#define MROWS   (T_STEPS * B_SZ)     // 32768

typedef unsigned long long ull;

// ---------------- device scratch (no allocation allowed) ----------------
__device__ float g_gates[(size_t)T_STEPS * B_SZ * G4];   // [t][b][p], p = 4j+g
__device__ float g_wih_p[G4 * I_SZ];                     // packed W_ih (p = 4j+g)
__device__ float g_bias_p[G4];                           // b_ih + b_hh, packed
__device__ unsigned g_hpkHi[NG * 2 * 2048];              // [grp][ph][k2][b8] bf16x2 hi
__device__ unsigned g_hpkLo[NG * 2 * 2048];              // [grp][ph][k2][b8] bf16x2 lo
__device__ unsigned g_cnt[NG * 8 * 32];                  // per-(group,quarter) arrival counters
// W_hh HMMA fragments (per CTA: 16384 u32, uint4-ordered per thread) — R13/R14 layout
__device__ unsigned g_wfragHi[NC * 16384];
__device__ unsigned g_wfragLo[NC * 16384];
// bf16x3 GEMM operands
__device__ __nv_bfloat16 g_Ahi[(size_t)MROWS * I_SZ];
__device__ __nv_bfloat16 g_Alo[(size_t)MROWS * I_SZ];
__device__ __nv_bfloat16 g_Whi[G4 * I_SZ];
__device__ __nv_bfloat16 g_Wlo[G4 * I_SZ];

// ---------------- helpers ----------------
__device__ __forceinline__ void fadd2(ull &d, ull a) {
    asm("add.rn.f32x2 %0, %1, %2;" : "=l"(d) : "l"(d), "l"(a));
}
__device__ __forceinline__ float2 unpack2(ull v) {
    float2 r; asm("mov.b64 {%0, %1}, %2;" : "=f"(r.x), "=f"(r.y) : "l"(v)); return r;
}
__device__ __forceinline__ ull packf2(float a, float b) {
    ull r; asm("mov.b64 %0, {%1, %2};" : "=l"(r) : "f"(a), "f"(b)); return r;
}
__device__ __forceinline__ unsigned ld_acq(const unsigned* p) {
    unsigned v; asm volatile("ld.acquire.gpu.global.u32 %0, [%1];" : "=r"(v) : "l"(p) : "memory");
    return v;
}
__device__ __forceinline__ unsigned atom_add_rel(unsigned* p, unsigned v) {
    unsigned old;
    asm volatile("atom.add.release.gpu.global.u32 %0, [%1], %2;"
                 : "=r"(old) : "l"(p), "r"(v) : "memory");
    return old;
}
__device__ __forceinline__ unsigned ldcg_u32(const unsigned* p) {
    unsigned v; asm volatile("ld.global.cg.u32 %0, [%1];" : "=r"(v) : "l"(p));
    return v;
}
__device__ __forceinline__ float sigf(float x) {
    return __fdividef(1.f, 1.f + __expf(-x));
}
__device__ __forceinline__ float tanh_fast(float x) {
    float ax = fabsf(x);
    float e  = __expf(-2.f * ax);
    float r  = __fdividef(1.f - e, 1.f + e);
    return copysignf(r, x);
}
__device__ __forceinline__ void mma16816(float* c, const unsigned* a, const unsigned* b) {
    asm volatile(
        "mma.sync.aligned.m16n8k16.row.col.f32.bf16.bf16.f32 "
        "{%0,%1,%2,%3}, {%4,%5,%6,%7}, {%8,%9}, {%0,%1,%2,%3};"
        : "+f"(c[0]), "+f"(c[1]), "+f"(c[2]), "+f"(c[3])
        : "r"(a[0]), "r"(a[1]), "r"(a[2]), "r"(a[3]), "r"(b[0]), "r"(b[1]));
}
// fp32 pair -> packed bf16 hi + residual lo (low 16 bits = first element)
#define CVT2(f0, f1, HI, LO) do {                                   \
    __nv_bfloat162 _h = __floats2bfloat162_rn((f0), (f1));          \
    float _r0 = (f0) - __low2float(_h);                             \
    float _r1 = (f1) - __high2float(_h);                            \
    __nv_bfloat162 _l = __floats2bfloat162_rn(_r0, _r1);            \
    (HI) = *(unsigned*)&_h; (LO) = *(unsigned*)&_l;                 \
} while (0)

// ---------------- prep: pack W_ih, W_hh fragments (R13/R14 layout), packed h0, sync ----
__global__ void prep_kernel(const float* __restrict__ Wih, const float* __restrict__ Whh,
                            const float* __restrict__ bih, const float* __restrict__ bhh,
                            const float* __restrict__ h0) {
    int p = blockIdx.x;                     // packed row p = 4j + g
    int g = p & 3, j = p >> 2;
    int orig = g * H_SZ + j;

    const float* srcI = Wih + (size_t)orig * I_SZ;
    float* dI = g_wih_p + (size_t)p * I_SZ;
    for (int k = threadIdx.x; k < I_SZ; k += blockDim.x) dI[k] = srcI[k];

    // W_hh -> per-thread HMMA fragment order (bf16 hi/lo), R13/R14 layout
    const float* srcH = Whh + (size_t)orig * H_SZ;
    int cc = p >> 6, r = p & 63;
    int ma = r >> 4, rr = r & 15;
    for (int k = threadIdx.x; k < H_SZ; k += blockDim.x) {
        float w = srcH[k];
        __nv_bfloat16 hb = __float2bfloat16(w);
        __nv_bfloat16 lb = __float2bfloat16(w - __bfloat162float(hb));
        int kq = k >> 6, ka = (k >> 4) & 3, kin = k & 15;
        int q = (rr >= 8 ? 1 : 0) + (kin >= 8 ? 2 : 0);
        int lane = (rr & 7) * 4 + ((kin & 7) >> 1);
        size_t u16idx = (((size_t)cc * 16384 + ((ma * 4 + ka) * 256 + kq * 32 + lane) * 4 + q) << 1)
                        + (k & 1);
        ((unsigned short*)g_wfragHi)[u16idx] = __bfloat16_as_ushort(hb);
        ((unsigned short*)g_wfragLo)[u16idx] = __bfloat16_as_ushort(lb);
    }
    if (threadIdx.x == 0) g_bias_p[p] = bih[orig] + bhh[orig];

    // h0 -> packed bf16 hi/lo pairs, consumer layout [grp][0][k2][b8]
    if (p < H_SZ && !(p & 1)) {
        for (int b = threadIdx.x; b < B_SZ; b += blockDim.x) {
            unsigned hi, lo;
            CVT2(h0[(size_t)b * H_SZ + p], h0[(size_t)b * H_SZ + p + 1], hi, lo);
            int idx = (b >> 3) * 2 * 2048 + (p >> 1) * 8 + (b & 7);
            g_hpkHi[idx] = hi; g_hpkLo[idx] = lo;
        }
    }
    if (p < NG * 8 && threadIdx.x == 0) g_cnt[p * 32] = 0;
}

// ---------------- convert: fp32 -> bf16 hi/lo for A (input) and packed W_ih ------------
__global__ __launch_bounds__(256) void convert_kernel(const float* __restrict__ input) {
    int bid = blockIdx.x;
    const float* src;
    __nv_bfloat16 *dhi, *dlo;
    size_t i;
    if (bid < 8192) {
        i = ((size_t)bid * 256 + threadIdx.x) * 8;
        src = input; dhi = g_Ahi; dlo = g_Alo;
    } else {
        i = ((size_t)(bid - 8192) * 256 + threadIdx.x) * 8;
        src = g_wih_p; dhi = g_Whi; dlo = g_Wlo;
    }
    float4 x0 = *(const float4*)(src + i);
    float4 x1 = *(const float4*)(src + i + 4);
    float v[8] = {x0.x, x0.y, x0.z, x0.w, x1.x, x1.y, x1.z, x1.w};
    unsigned hs[4], ls[4];
#pragma unroll
    for (int k = 0; k < 4; k++) CVT2(v[2 * k], v[2 * k + 1], hs[k], ls[k]);
    *(uint4*)(dhi + i) = make_uint4(hs[0], hs[1], hs[2], hs[3]);
    *(uint4*)(dlo + i) = make_uint4(ls[0], ls[1], ls[2], ls[3]);
}

// ---------------- phase 1: bf16x3 HMMA GEMM, register double-buffered (R14-exact) ------
#define GPITCH 40

__global__ __launch_bounds__(256) void gemm_tc_kernel() {
    __shared__ __nv_bfloat16 sAh[128][GPITCH];
    __shared__ __nv_bfloat16 sAl[128][GPITCH];
    __shared__ __nv_bfloat16 sBh[128][GPITCH];
    __shared__ __nv_bfloat16 sBl[128][GPITCH];

    int tid  = threadIdx.x;
    int lane = tid & 31, wid = tid >> 5;
    int wm = wid & 3, wn = wid >> 2;
    int mBase = blockIdx.y * 128;
    int nBase = blockIdx.x * 128;

    int lrow = tid >> 1, lhalf = tid & 1;

    float acc[2][8][4];
#pragma unroll
    for (int ma = 0; ma < 2; ma++)
#pragma unroll
        for (int na = 0; na < 8; na++)
#pragma unroll
            for (int q = 0; q < 4; q++) acc[ma][na][q] = 0.f;

    int fr = lane >> 2;
    int fc = (lane & 3) * 2;

    size_t gaRow = (size_t)(mBase + lrow) * I_SZ + lhalf * 16;
    size_t gbRow = (size_t)(nBase + lrow) * I_SZ + lhalf * 16;
    uint4 ra0 = __ldg((const uint4*)(g_Ahi + gaRow));
    uint4 ra1 = __ldg((const uint4*)(g_Ahi + gaRow) + 1);
    uint4 rl0 = __ldg((const uint4*)(g_Alo + gaRow));
    uint4 rl1 = __ldg((const uint4*)(g_Alo + gaRow) + 1);
    uint4 rb0 = __ldg((const uint4*)(g_Whi + gbRow));
    uint4 rb1 = __ldg((const uint4*)(g_Whi + gbRow) + 1);
    uint4 rq0 = __ldg((const uint4*)(g_Wlo + gbRow));
    uint4 rq1 = __ldg((const uint4*)(g_Wlo + gbRow) + 1);

    for (int ks = 0; ks < I_SZ / 32; ks++) {
        *(uint4*)&sAh[lrow][lhalf * 16]     = ra0;
        *(uint4*)&sAh[lrow][lhalf * 16 + 8] = ra1;
        *(uint4*)&sAl[lrow][lhalf * 16]     = rl0;
        *(uint4*)&sAl[lrow][lhalf * 16 + 8] = rl1;
        *(uint4*)&sBh[lrow][lhalf * 16]     = rb0;
        *(uint4*)&sBh[lrow][lhalf * 16 + 8] = rb1;
        *(uint4*)&sBl[lrow][lhalf * 16]     = rq0;
        *(uint4*)&sBl[lrow][lhalf * 16 + 8] = rq1;
        __syncthreads();

        if (ks + 1 < I_SZ / 32) {
            size_t ga = gaRow + (ks + 1) * 32;
            size_t gb = gbRow + (ks + 1) * 32;
            ra0 = __ldg((const uint4*)(g_Ahi + ga));
            ra1 = __ldg((const uint4*)(g_Ahi + ga) + 1);
            rl0 = __ldg((const uint4*)(g_Alo + ga));
            rl1 = __ldg((const uint4*)(g_Alo + ga) + 1);
            rb0 = __ldg((const uint4*)(g_Whi + gb));
            rb1 = __ldg((const uint4*)(g_Whi + gb) + 1);
            rq0 = __ldg((const uint4*)(g_Wlo + gb));
            rq1 = __ldg((const uint4*)(g_Wlo + gb) + 1);
        }

#pragma unroll
        for (int ka = 0; ka < 2; ka++) {
            int kc = ka * 16 + fc;
            unsigned aH[2][4], aL[2][4];
#pragma unroll
            for (int ma = 0; ma < 2; ma++) {
                int r0 = wm * 32 + ma * 16 + fr;
                aH[ma][0] = *(const unsigned*)&sAh[r0][kc];
                aH[ma][1] = *(const unsigned*)&sAh[r0 + 8][kc];
                aH[ma][2] = *(const unsigned*)&sAh[r0][kc + 8];
                aH[ma][3] = *(const unsigned*)&sAh[r0 + 8][kc + 8];
                aL[ma][0] = *(const unsigned*)&sAl[r0][kc];
                aL[ma][1] = *(const unsigned*)&sAl[r0 + 8][kc];
                aL[ma][2] = *(const unsigned*)&sAl[r0][kc + 8];
                aL[ma][3] = *(const unsigned*)&sAl[r0 + 8][kc + 8];
            }
            unsigned bH[8][2], bL[8][2];
#pragma unroll
            for (int na = 0; na < 8; na++) {
                int n0 = wn * 64 + na * 8 + fr;
                bH[na][0] = *(const unsigned*)&sBh[n0][kc];
                bH[na][1] = *(const unsigned*)&sBh[n0][kc + 8];
                bL[na][0] = *(const unsigned*)&sBl[n0][kc];
                bL[na][1] = *(const unsigned*)&sBl[n0][kc + 8];
            }
#pragma unroll
            for (int ma = 0; ma < 2; ma++)
#pragma unroll
                for (int na = 0; na < 8; na++) {
                    mma16816(acc[ma][na], aH[ma], bH[na]);
                    mma16816(acc[ma][na], aH[ma], bL[na]);
                    mma16816(acc[ma][na], aL[ma], bH[na]);
                }
        }
        __syncthreads();
    }

#pragma unroll
    for (int ma = 0; ma < 2; ma++)
#pragma unroll
        for (int na = 0; na < 8; na++) {
            int row = mBase + wm * 32 + ma * 16 + fr;
            int col = nBase + wn * 64 + na * 8 + fc;
            float b0 = __ldg(&g_bias_p[col]);
            float b1 = __ldg(&g_bias_p[col + 1]);
            float* d0 = g_gates + (size_t)row * G4 + col;
            d0[0] = acc[ma][na][0] + b0;
            d0[1] = acc[ma][na][1] + b1;
            float* d1 = d0 + (size_t)8 * G4;
            d1[0] = acc[ma][na][2] + b0;
            d1[1] = acc[ma][na][3] + b1;
        }
}

// ---------------- phase 2: persistent scan (quarter-barriers + direct fragment loads) --
// Warp kq consumes k2 in [32kq, 32kq+32) — produced by CTAs [4kq, 4kq+4). Each warp
// polls ONLY its quarter counter (warp-local, lanes 0-3 + __any_sync, no CTA bar),
// then loads its MMA b-fragments DIRECTLY from global (fully coalesced 128B lines).
// Publish barrier is bar.sync 1,128 (lo threads); hi warps run ahead into t+1's
// poll/LDG/MMA during the epilogue tail, stalling only at the next dump-syncthreads.
__global__ __launch_bounds__(256) void scan_kernel(const float* __restrict__ c0,
                                                   float* __restrict__ out, int out_size) {
    extern __shared__ float smem[];
    ull*   sh_part = (ull*)smem;                   // 256*9 ull (18 KB)
    float* sh_gate = smem + 4608;                  // 64 rows * 10 floats

    int tid = threadIdx.x;
    int grp = blockIdx.x >> 5;
    int c   = blockIdx.x & 31;
    int lane = tid & 31, kq = tid >> 5;

    // W_hh fragments -> registers (constant for all 1024 steps)
    uint4 wHi[16], wLo[16];
    {
        const uint4* fh = ((const uint4*)g_wfragHi) + c * 4096;
        const uint4* fl = ((const uint4*)g_wfragLo) + c * 4096;
#pragma unroll
        for (int i = 0; i < 16; i++) {
            wHi[i] = __ldg(fh + i * 256 + tid);
            wLo[i] = __ldg(fl + i * 256 + tid);
        }
    }

    int b8 = tid >> 4, jl = tid & 15;            // epilogue mapping (tid < 128)
    float c_val = 0.f;
    const float* gxp = g_gates;
    if (tid < 128) {
        c_val = c0[(size_t)(grp * 8 + b8) * H_SZ + c * 16 + jl];
        gxp   = g_gates + (size_t)(grp * 8 + b8) * G4 + c * 64 + jl * 4;
    }
    unsigned* cntQ = &g_cnt[(grp * 8 + kq) * 32];         // this warp's wait counter
    unsigned* cntA = &g_cnt[(grp * 8 + (c >> 2)) * 32];   // this CTA's arrival counter
    unsigned* gHi = g_hpkHi + grp * 2 * 2048;
    unsigned* gLo = g_hpkLo + grp * 2 * 2048;

    int n = lane >> 2;

    for (int t = 0; t < T_STEPS; t++) {
        float4 gxv = make_float4(0.f, 0.f, 0.f, 0.f);
        if (tid < 128) gxv = __ldg((const float4*)(gxp + (size_t)t * B_SZ * G4));

        // ---- warp-local quarter wait (lanes 0-3 poll, __any_sync releases warp) ----
        {
            unsigned tgt = (unsigned)t * (unsigned)NCQ;
            for (;;) {
                unsigned v = (lane < 4) ? ld_acq(cntQ) : 0u;
                if (__any_sync(0xffffffffu, (lane < 4) && v >= tgt)) break;
            }
        }

        // ---- direct b-fragment loads from global (each warp: 16 coalesced lines) ----
        const unsigned* hHiP = gHi + (t & 1) * 2048;
        const unsigned* hLoP = gLo + (t & 1) * 2048;
        unsigned bhv[4][2], blv[4][2];
#pragma unroll
        for (int ka = 0; ka < 4; ka++) {
            int k2b = kq * 32 + ka * 8 + (lane & 3);
            bhv[ka][0] = ldcg_u32(hHiP + k2b * 8 + n);
            bhv[ka][1] = ldcg_u32(hHiP + (k2b + 4) * 8 + n);
            blv[ka][0] = ldcg_u32(hLoP + k2b * 8 + n);
            blv[ka][1] = ldcg_u32(hLoP + (k2b + 4) * 8 + n);
        }

        // ---- HMMA bf16x3: 4 m-atoms x 4 k-atoms x 3 passes ----
        float acc[4][4];
#pragma unroll
        for (int ma = 0; ma < 4; ma++)
#pragma unroll
            for (int q = 0; q < 4; q++) acc[ma][q] = 0.f;
#pragma unroll
        for (int ka = 0; ka < 4; ka++) {
#pragma unroll
            for (int ma = 0; ma < 4; ma++) {
                const unsigned* aH = (const unsigned*)&wHi[ma * 4 + ka];
                const unsigned* aL = (const unsigned*)&wLo[ma * 4 + ka];
                mma16816(acc[ma], aH, bhv[ka]);
                mma16816(acc[ma], aH, blv[ka]);
                mma16816(acc[ma], aL, bhv[ka]);
            }
        }

        // ---- dump partials, parallel cross-kq reduce ----
        {
            ull* pp = sh_part + tid * 9;
#pragma unroll
            for (int ma = 0; ma < 4; ma++) {
                pp[ma * 2]     = packf2(acc[ma][0], acc[ma][1]);
                pp[ma * 2 + 1] = packf2(acc[ma][2], acc[ma][3]);
            }
        }
        __syncthreads();
        {
            int l = tid & 31, s = tid >> 5;
            ull v = sh_part[l * 9 + s];
#pragma unroll
            for (int k2 = 1; k2 < 8; k2++) fadd2(v, sh_part[((k2 << 5) + l) * 9 + s]);
            float2 vf = unpack2(v);
            int ma = s >> 1, half = s & 1;
            int row  = ma * 16 + (l >> 2) + 8 * half;
            int bcol = (l & 3) * 2;
            sh_gate[row * 10 + bcol]     = vf.x;
            sh_gate[row * 10 + bcol + 1] = vf.y;
        }
        __syncthreads();

        // ---- epilogue + producer-side bf16 packing + arrival (lo threads only) ----
        if (tid < 128) {
            const float* gr = sh_gate + (4 * jl) * 10 + b8;
            float pi = gr[0]  + gxv.x;
            float pf = gr[10] + gxv.y;
            float pg = gr[20] + gxv.z;
            float po = gr[30] + gxv.w;
            float ig = sigf(pi), fg = sigf(pf), og = sigf(po);
            float gg = tanh_fast(pg);
            c_val = fg * c_val + ig * gg;
            float h_new = og * tanh_fast(c_val);
            float hp = __shfl_xor_sync(0xffffffffu, h_new, 1);
            if (!(jl & 1)) {                     // even jl packs (h_j, h_j+1)
                unsigned hi, lo;
                CVT2(h_new, hp, hi, lo);
                int idx = ((t + 1) & 1) * 2048 + (c * 8 + (jl >> 1)) * 8 + b8;
                gHi[idx] = hi; gLo[idx] = lo;
            }
            asm volatile("bar.sync 1, 128;" ::: "memory");   // publish visible (lo threads)
            if (tid == 0) atom_add_rel(cntA, 1u);            // release = signal
            out[(size_t)t * BH + (size_t)(grp * 8 + b8) * H_SZ + c * 16 + jl] = h_new;
            if (t == T_STEPS - 1 && out_size >= TBH + 2 * BH) {
                out[TBH + (grp * 8 + b8) * H_SZ + c * 16 + jl]      = h_new;  // h_f
                out[TBH + BH + (grp * 8 + b8) * H_SZ + c * 16 + jl] = c_val;  // c_f
            }
        }
        // hi warps proceed straight to t+1 poll/LDG/MMA; they rejoin at dump-syncthreads
    }
}

// ---------------- launch ----------------
extern "C" void kernel_launch(void* const* d_in, const int* in_sizes, int n_in,
                              void* d_out, int out_size) {
    const float* input = (const float*)d_in[0];
    const float* h0    = (const float*)d_in[1];
    const float* c0    = (const float*)d_in[2];
    const float* Wih   = (const float*)d_in[3];
    const float* Whh   = (const float*)d_in[4];
    const float* bih   = (const float*)d_in[5];
    const float* bhh   = (const float*)d_in[6];
    float* out = (float*)d_out;

    prep_kernel<<<G4, 128>>>(Wih, Whh, bih, bhh, h0);
    convert_kernel<<<8192 + 512, 256>>>(input);

    dim3 gridG(G4 / 128, MROWS / 128);
    gemm_tc_kernel<<<gridG, 256>>>();

    const int scan_smem = (4608 + 640) * (int)sizeof(float);  // 20992 B
    cudaFuncSetAttribute(scan_kernel, cudaFuncAttributeMaxDynamicSharedMemorySize, scan_smem);
    scan_kernel<<<NG * NC, 256, scan_smem>>>(c0, out, out_size);
}